// round 1
// baseline (speedup 1.0000x reference)
#include <cuda_runtime.h>
#include <cuda_bf16.h>
#include <cstdint>

// Problem constants
#define N_TOTAL 16384      // B*H*W = 16*32*32
#define C_DIM   128
#define K_CODES 8192
#define HW      1024       // H*W per batch image
#define B_DIM   16

// Scratch (device globals: no allocation allowed)
__device__ float g_sumw2[K_CODES];
__device__ int   g_ids[N_TOTAL];
__device__ float g_counts[K_CODES];
__device__ float g_sums[K_CODES * C_DIM];

// ---------------------------------------------------------------------------
// K1: sum of squares per codebook row (one warp per row)
// ---------------------------------------------------------------------------
__global__ void sumw2_kernel(const float* __restrict__ w) {
    int k    = blockIdx.x * 8 + (threadIdx.x >> 5);
    int lane = threadIdx.x & 31;
    const float* row = w + k * C_DIM;
    float s = 0.f;
#pragma unroll
    for (int j = 0; j < 4; j++) {
        float v = row[lane + j * 32];
        s = fmaf(v, v, s);
    }
#pragma unroll
    for (int off = 16; off; off >>= 1)
        s += __shfl_xor_sync(0xffffffffu, s, off);
    if (lane == 0) g_sumw2[k] = s;
}

// ---------------------------------------------------------------------------
// K2: fused distance + argmin.
// Block: 256 threads, tile = 64 rows (n) x 64 codes (k), full C=128 reduction.
// Both tiles stored in smem with c-pairs interleaved so that ulonglong2 loads
// feed fma.rn.f32x2 (packed fp32x2 FMA: 2x fp32 throughput per fma-pipe issue).
//   xs layout: [c2][n][2]   stride 128 floats per c2
//   ws layout: [c2][k][2]   stride 132 floats per c2 (pad keeps 16B alignment,
//                            write pattern step 132 -> 2-way max conflict)
// ---------------------------------------------------------------------------
#define XS_FLOATS  (64 * 128)                   // 8192
#define WS_STRIDE  132
#define WS_FLOATS  (64 * WS_STRIDE)             // 8448
#define SMEM_FLOATS (XS_FLOATS + WS_FLOATS + 64 + 64 + 1024 + 1024)
#define SMEM_BYTES (SMEM_FLOATS * 4)

__global__ void __launch_bounds__(256)
dist_argmin_kernel(const float* __restrict__ enc,
                   const float* __restrict__ w,
                   float* __restrict__ out_ids) {
    extern __shared__ float sm[];
    float* xs   = sm;                       // 8192
    float* ws   = xs + XS_FLOATS;           // 8448
    float* swt  = ws + WS_FLOATS;           // 64
    float* sx2  = swt + 64;                 // 64
    float* redD = sx2 + 64;                 // 1024
    int*   redI = (int*)(redD + 1024);      // 1024

    const int t  = threadIdx.x;
    const int tx = t & 15;                  // k-group (4 codes)
    const int ty = t >> 4;                  // n-group (4 rows)
    const int n0 = blockIdx.x * 64;

    // x[n][c] = enc[b*C*HW + c*HW + hw]; a 64-row tile stays inside one b.
    const float* xbase = enc + (n0 >> 10) * (C_DIM * HW) + (n0 & (HW - 1));

    // Load x tile (coalesced along n), store pair-interleaved.
#pragma unroll
    for (int i = 0; i < 32; i++) {
        int lin = i * 256 + t;
        int c   = lin >> 6;
        int nl  = lin & 63;
        xs[(c >> 1) * 128 + nl * 2 + (c & 1)] = xbase[c * HW + nl];
    }
    __syncthreads();

    // per-row ||x||^2 (threads 0..63)
    if (t < 64) {
        float s = 0.f;
        for (int c2 = 0; c2 < 64; c2++) {
            float v0 = xs[c2 * 128 + t * 2];
            float v1 = xs[c2 * 128 + t * 2 + 1];
            s = fmaf(v0, v0, s);
            s = fmaf(v1, v1, s);
        }
        sx2[t] = s;
    }

    float bestd[4];
    int   besti[4];
#pragma unroll
    for (int i = 0; i < 4; i++) { bestd[i] = 3.4e38f; besti[i] = 0; }

    for (int k0 = 0; k0 < K_CODES; k0 += 64) {
        __syncthreads();   // previous tile fully consumed (also covers sx2 on iter 0)

        // Load w tile (coalesced along c), transpose into pair-interleaved layout.
        const float* wb = w + k0 * C_DIM;
#pragma unroll
        for (int i = 0; i < 32; i++) {
            int lin = i * 256 + t;
            int kl  = lin >> 7;
            int c   = lin & 127;
            ws[(c >> 1) * WS_STRIDE + kl * 2 + (c & 1)] = wb[kl * C_DIM + c];
        }
        if (t < 64) swt[t] = g_sumw2[k0 + t];
        __syncthreads();

        unsigned long long acc[4][4];
#pragma unroll
        for (int i = 0; i < 4; i++)
#pragma unroll
            for (int j = 0; j < 4; j++) acc[i][j] = 0ull;  // (0.f, 0.f)

        const float* xp = xs + ty * 8;
        const float* wp = ws + tx * 8;
#pragma unroll 4
        for (int c2 = 0; c2 < 64; c2++) {
            ulonglong2 a01 = *(const ulonglong2*)(xp);
            ulonglong2 a23 = *(const ulonglong2*)(xp + 4);
            ulonglong2 b01 = *(const ulonglong2*)(wp);
            ulonglong2 b23 = *(const ulonglong2*)(wp + 4);
            unsigned long long A[4]  = {a01.x, a01.y, a23.x, a23.y};
            unsigned long long Bv[4] = {b01.x, b01.y, b23.x, b23.y};
#pragma unroll
            for (int i = 0; i < 4; i++)
#pragma unroll
                for (int j = 0; j < 4; j++)
                    asm("fma.rn.f32x2 %0, %1, %2, %0;"
                        : "+l"(acc[i][j]) : "l"(A[i]), "l"(Bv[j]));
            xp += 128;
            wp += WS_STRIDE;
        }

        // Epilogue: dist = round32(sx2 + sw2) - round32(2*dot), mimicking the
        // reference's fp32 op-by-op rounding so sub-ulp ties resolve the same way.
#pragma unroll
        for (int i = 0; i < 4; i++) {
            float sxv = sx2[ty * 4 + i];
#pragma unroll
            for (int j = 0; j < 4; j++) {
                unsigned long long v = acc[i][j];
                float lo = __uint_as_float((unsigned int)(v & 0xffffffffull));
                float hi = __uint_as_float((unsigned int)(v >> 32));
                float dot = lo + hi;
                float d = __fsub_rn(__fadd_rn(sxv, swt[tx * 4 + j]), 2.0f * dot);
                int   k = k0 + tx * 4 + j;
                if (d < bestd[i]) { bestd[i] = d; besti[i] = k; }
            }
        }
    }

    // Cross-thread argmin reduction (tie -> lowest index, matching jnp.argmin).
    __syncthreads();
#pragma unroll
    for (int i = 0; i < 4; i++) {
        int row = ty * 4 + i;
        redD[row * 16 + tx] = bestd[i];
        redI[row * 16 + tx] = besti[i];
    }
    __syncthreads();
    if (t < 64) {
        float bd = redD[t * 16];
        int   bi = redI[t * 16];
#pragma unroll
        for (int x = 1; x < 16; x++) {
            float d  = redD[t * 16 + x];
            int   id = redI[t * 16 + x];
            if (d < bd || (d == bd && id < bi)) { bd = d; bi = id; }
        }
        g_ids[n0 + t]   = bi;
        out_ids[n0 + t] = (float)bi;
    }
}

// ---------------------------------------------------------------------------
// K3: zero EMA scratch (must be re-zeroed every launch; graph replays)
// ---------------------------------------------------------------------------
__global__ void zero_kernel() {
    int i = blockIdx.x * 256 + threadIdx.x;
    if (i < K_CODES * C_DIM) g_sums[i] = 0.f;
    if (i < K_CODES)         g_counts[i] = 0.f;
}

// ---------------------------------------------------------------------------
// K4: scatter counts and per-channel sums (coalesced loads, spread REDG)
// ---------------------------------------------------------------------------
__global__ void scatter_kernel(const float* __restrict__ enc) {
    __shared__ int ids_s[128];
    int n0 = blockIdx.x * 128;
    int t  = threadIdx.x;
    ids_s[t] = g_ids[n0 + t];
    __syncthreads();
    const float* xb = enc + (n0 >> 10) * (C_DIM * HW) + (n0 & (HW - 1));
    atomicAdd(&g_counts[ids_s[t]], 1.0f);
    int id = ids_s[t];
    for (int c = 0; c < C_DIM; c++) {
        float v = xb[c * HW + t];
        atomicAdd(&g_sums[id * C_DIM + c], v);
    }
}

// ---------------------------------------------------------------------------
// K5a: q output. q[b][c][hw] = weight[ids[b*HW+hw]][c]  (forward value of STE)
// ---------------------------------------------------------------------------
__global__ void q_kernel(const float* __restrict__ w, float* __restrict__ outq) {
    int idx = blockIdx.x * 256 + threadIdx.x;
    if (idx >= N_TOTAL * C_DIM) return;
    int hw = idx & (HW - 1);
    int c  = (idx >> 10) & (C_DIM - 1);
    int b  = idx >> 17;
    int id = g_ids[b * HW + hw];
    outq[idx] = w[id * C_DIM + c];
}

// ---------------------------------------------------------------------------
// K5b: EMA codebook update
// ---------------------------------------------------------------------------
__global__ void neww_kernel(const float* __restrict__ w, float* __restrict__ outw) {
    int idx = blockIdx.x * 256 + threadIdx.x;
    if (idx >= K_CODES * C_DIM) return;
    int   k    = idx >> 7;
    float cnt  = g_counts[k];
    float mean = g_sums[idx] / (cnt + 1e-12f);
    outw[idx]  = 0.99f * w[idx] + 0.01f * mean;
}

// ---------------------------------------------------------------------------
extern "C" void kernel_launch(void* const* d_in, const int* in_sizes, int n_in,
                              void* d_out, int out_size) {
    const float* enc = (const float*)d_in[0];   // [16,128,32,32]
    const float* w   = (const float*)d_in[1];   // [8192,128]
    float* out      = (float*)d_out;
    float* out_ids  = out;                       // 16384
    float* out_q    = out + N_TOTAL;             // 2097152
    float* out_w    = out + N_TOTAL + N_TOTAL * C_DIM;  // 1048576

    cudaFuncSetAttribute(dist_argmin_kernel,
                         cudaFuncAttributeMaxDynamicSharedMemorySize, SMEM_BYTES);

    sumw2_kernel<<<K_CODES / 8, 256>>>(w);
    zero_kernel<<<(K_CODES * C_DIM + 255) / 256, 256>>>();
    dist_argmin_kernel<<<N_TOTAL / 64, 256, SMEM_BYTES>>>(enc, w, out_ids);
    scatter_kernel<<<N_TOTAL / 128, 128>>>(enc);
    q_kernel<<<(N_TOTAL * C_DIM + 255) / 256, 256>>>(w, out_q);
    neww_kernel<<<(K_CODES * C_DIM + 255) / 256, 256>>>(w, out_w);
}

// round 4
// speedup vs baseline: 2.4073x; 2.4073x over previous
#include <cuda_runtime.h>
#include <cuda_bf16.h>
#include <cstdint>

#define N_TOTAL 16384
#define C_DIM   128
#define K_CODES 8192
#define HW      1024

// ---------------- device scratch ----------------
__device__ float g_sumw2[K_CODES];
__device__ float g_sumx2[N_TOTAL];
__device__ int   g_ids[N_TOTAL];
__device__ float g_counts[K_CODES];
__device__ float g_sums[K_CODES * C_DIM];
__device__ unsigned long long g_best[N_TOTAL];
__device__ __nv_bfloat16 g_wsp[3][K_CODES * C_DIM];
__device__ __nv_bfloat16 g_xsp[3][N_TOTAL * C_DIM];

// ---------------- helpers ----------------
__device__ __forceinline__ uint32_t smem_u32(const void* p) {
    uint32_t a;
    asm("{ .reg .u64 t; cvta.to.shared.u64 t, %1; cvt.u32.u64 %0, t; }" : "=r"(a) : "l"(p));
    return a;
}
__device__ __forceinline__ void cp16(uint32_t s, const void* g) {
    asm volatile("cp.async.cg.shared.global [%0], [%1], 16;" :: "r"(s), "l"(g) : "memory");
}
#define CP_COMMIT() asm volatile("cp.async.commit_group;" ::: "memory")
#define SWZ(b) ((b) ^ (((b) >> 3) & 0x70))

#define LDSM4(r, a) \
    asm volatile("ldmatrix.sync.aligned.m8n8.x4.shared.b16 {%0,%1,%2,%3}, [%4];" \
        : "=r"((r)[0]), "=r"((r)[1]), "=r"((r)[2]), "=r"((r)[3]) : "r"(a))

#define MMA(c, a, b0v, b1v) \
    asm volatile("mma.sync.aligned.m16n8k16.row.col.f32.bf16.bf16.f32 " \
        "{%0,%1,%2,%3},{%4,%5,%6,%7},{%8,%9},{%0,%1,%2,%3};" \
        : "+f"((c)[0]), "+f"((c)[1]), "+f"((c)[2]), "+f"((c)[3]) \
        : "r"((a)[0]), "r"((a)[1]), "r"((a)[2]), "r"((a)[3]), "r"(b0v), "r"(b1v))

// ---------------- K1a: split weight into 3 bf16 limbs ----------------
__global__ void split_w_kernel(const float* __restrict__ w) {
    int idx = blockIdx.x * 256 + threadIdx.x;
    float v = w[idx];
    __nv_bfloat16 h = __float2bfloat16(v);
    float r1 = v - __bfloat162float(h);
    __nv_bfloat16 m = __float2bfloat16(r1);
    float r2 = r1 - __bfloat162float(m);
    g_wsp[0][idx] = h;
    g_wsp[1][idx] = m;
    g_wsp[2][idx] = __float2bfloat16(r2);
}

// ---------------- K1b: ||w||^2 ----------------
__global__ void sumw2_kernel(const float* __restrict__ w) {
    int k = blockIdx.x * 8 + (threadIdx.x >> 5);
    int lane = threadIdx.x & 31;
    const float* row = w + k * C_DIM;
    float s = 0.f;
#pragma unroll
    for (int j = 0; j < 4; j++) { float v = row[lane + j * 32]; s = fmaf(v, v, s); }
#pragma unroll
    for (int off = 16; off; off >>= 1) s += __shfl_xor_sync(0xffffffffu, s, off);
    if (lane == 0) g_sumw2[k] = s;
}

// ---------------- K1c: transpose x, split, ||x||^2 ----------------
__global__ void prep_x_kernel(const float* __restrict__ enc) {
    __shared__ float sm[128 * 64];
    int t = threadIdx.x;
    int n0 = blockIdx.x * 64;
    const float* xb = enc + (n0 >> 10) * (C_DIM * HW) + (n0 & (HW - 1));
#pragma unroll
    for (int i = 0; i < 32; i++) {
        int lin = i * 256 + t, c = lin >> 6, nl = lin & 63;
        sm[c * 64 + nl] = xb[c * HW + nl];
    }
    __syncthreads();
#pragma unroll
    for (int i = 0; i < 32; i++) {
        int lin = i * 256 + t, n = lin >> 7, c = lin & 127;
        float v = sm[c * 64 + n];
        __nv_bfloat16 h = __float2bfloat16(v);
        float r1 = v - __bfloat162float(h);
        __nv_bfloat16 m = __float2bfloat16(r1);
        float r2 = r1 - __bfloat162float(m);
        int idx = (n0 + n) * C_DIM + c;
        g_xsp[0][idx] = h;
        g_xsp[1][idx] = m;
        g_xsp[2][idx] = __float2bfloat16(r2);
    }
    if (t < 64) {
        float s = 0.f;
        for (int c = 0; c < 128; c++) { float v = sm[c * 64 + t]; s = fmaf(v, v, s); }
        g_sumx2[n0 + t] = s;
    }
}

// ---------------- K2: init scratch ----------------
__global__ void zero_kernel() {
    int i = blockIdx.x * 256 + threadIdx.x;
    if (i < K_CODES * C_DIM) g_sums[i] = 0.f;
    if (i < K_CODES)         g_counts[i] = 0.f;
    if (i < N_TOTAL)         g_best[i] = ~0ull;
}

// ---------------- K3: tensor GEMM dist + argmin ----------------
// CTA tile 128(M) x 256(N), K_eff = 768 (6 limb products x 128), chunks of 64.
// 8 warps, warp tile 64x64, mma m16n8k16 bf16->f32.
#define STAGE_BYTES 49152          // A 16KB + B 32KB
#define OFF_SW2     98304
#define OFF_SX2     99328
#define DSMEM_BYTES 99840

__global__ void __launch_bounds__(256)
dist_kernel() {
    extern __shared__ char sm[];
    const uint32_t sb = smem_u32(sm);
    const int t = threadIdx.x, l = t & 31, wi = t >> 5;
    const int wm = wi >> 2, wn = wi & 3;          // 2 x 4 warp grid
    const int m0 = blockIdx.y * 128, n0 = blockIdx.x * 256;

    float* sw2s = (float*)(sm + OFF_SW2);
    float* sx2s = (float*)(sm + OFF_SX2);
    sw2s[t] = g_sumw2[n0 + t];
    if (t < 128) sx2s[t] = g_sumx2[m0 + t];

    auto issue = [&](int cc, int st) {
        int pr = cc >> 1, koff = (cc & 1) * 64;
        int sa = (0x210100 >> (pr * 4)) & 7;  // SA = 0,0,1,0,1,2
        int sbl = (0x012010 >> (pr * 4)) & 7; // SB = 0,1,0,2,1,0
        const __nv_bfloat16* ga = &g_xsp[sa][(size_t)m0 * 128 + koff];
        const __nv_bfloat16* gb = &g_wsp[sbl][(size_t)n0 * 128 + koff];
        uint32_t abase = sb + st * STAGE_BYTES;
        uint32_t bbase = abase + 16384;
        // A tile: 128 rows x 64 bf16 = 1024 x 16B chunks
#pragma unroll
        for (int u = t; u < 1024; u += 256) {
            int r = u >> 3, c16 = u & 7;
            cp16(abase + SWZ(r * 128 + c16 * 16), ga + r * 128 + c16 * 8);
        }
        // B tile: 256 rows x 64 bf16 = 2048 x 16B chunks
#pragma unroll
        for (int u = t; u < 2048; u += 256) {
            int r = u >> 3, c16 = u & 7;
            cp16(bbase + SWZ(r * 128 + c16 * 16), gb + r * 128 + c16 * 8);
        }
    };

    float acc[4][8][4];
#pragma unroll
    for (int mi = 0; mi < 4; mi++)
#pragma unroll
        for (int ni = 0; ni < 8; ni++)
#pragma unroll
            for (int c = 0; c < 4; c++) acc[mi][ni][c] = 0.f;

    issue(0, 0); CP_COMMIT();
    issue(1, 1); CP_COMMIT();

    for (int cc = 0; cc < 12; cc++) {
        const int st = cc & 1;
        asm volatile("cp.async.wait_group 1;" ::: "memory");
        __syncthreads();
        const uint32_t abase = sb + st * STAGE_BYTES;
        const uint32_t bbase = abase + 16384;
#pragma unroll
        for (int ks = 0; ks < 4; ks++) {
            uint32_t a[4][4], b[4][4];
#pragma unroll
            for (int mi = 0; mi < 4; mi++) {
                int row = wm * 64 + mi * 16 + (l & 15);
                LDSM4(a[mi], abase + SWZ(row * 128 + ks * 32 + ((l >> 4) * 16)));
            }
#pragma unroll
            for (int ni2 = 0; ni2 < 4; ni2++) {
                int row = wn * 64 + ni2 * 16 + ((l >> 4) << 3) + (l & 7);
                LDSM4(b[ni2], bbase + SWZ(row * 128 + ks * 32 + (((l >> 3) & 1) * 16)));
            }
#pragma unroll
            for (int mi = 0; mi < 4; mi++)
#pragma unroll
                for (int ni = 0; ni < 8; ni++)
                    MMA(acc[mi][ni], a[mi], b[ni >> 1][(ni & 1) * 2], b[ni >> 1][(ni & 1) * 2 + 1]);
        }
        __syncthreads();
        if (cc + 2 < 12) issue(cc + 2, st);
        CP_COMMIT();
    }

    // Epilogue: dist with reference-exact rounding; lexicographic (dist, idx) min.
#pragma unroll
    for (int mi = 0; mi < 4; mi++) {
#pragma unroll
        for (int half = 0; half < 2; half++) {
            int rl = wm * 64 + mi * 16 + (l >> 2) + half * 8;
            float sx = sx2s[rl];
            unsigned long long key = ~0ull;
#pragma unroll
            for (int ni = 0; ni < 8; ni++) {
#pragma unroll
                for (int c = 0; c < 2; c++) {
                    int col = wn * 64 + ni * 8 + (l & 3) * 2 + c;
                    float d = __fsub_rn(__fadd_rn(sx, sw2s[col]),
                                        2.0f * acc[mi][ni][half * 2 + c]);
                    unsigned long long k =
                        ((unsigned long long)__float_as_uint(d) << 32) | (unsigned)(n0 + col);
                    key = (k < key) ? k : key;
                }
            }
            unsigned long long o1 = __shfl_xor_sync(0xffffffffu, key, 1);
            key = (o1 < key) ? o1 : key;
            unsigned long long o2 = __shfl_xor_sync(0xffffffffu, key, 2);
            key = (o2 < key) ? o2 : key;
            if ((l & 3) == 0) atomicMin(&g_best[m0 + rl], key);
        }
    }
}

// ---------------- K4: finalize ids ----------------
__global__ void ids_kernel(float* __restrict__ out_ids) {
    int n = blockIdx.x * 256 + threadIdx.x;
    int bi = (int)(g_best[n] & 0xFFFFFFFFull);
    g_ids[n] = bi;
    out_ids[n] = (float)bi;
}

// ---------------- K5: scatter counts + sums ----------------
__global__ void scatter_kernel(const float* __restrict__ enc) {
    __shared__ int ids_s[128];
    int n0 = blockIdx.x * 128;
    int t = threadIdx.x;
    ids_s[t] = g_ids[n0 + t];
    __syncthreads();
    const float* xb = enc + (n0 >> 10) * (C_DIM * HW) + (n0 & (HW - 1));
    atomicAdd(&g_counts[ids_s[t]], 1.0f);
    int id = ids_s[t];
    for (int c = 0; c < C_DIM; c++) {
        float v = xb[c * HW + t];
        atomicAdd(&g_sums[id * C_DIM + c], v);
    }
}

// ---------------- K6a: q output ----------------
__global__ void q_kernel(const float* __restrict__ w, float* __restrict__ outq) {
    int idx = blockIdx.x * 256 + threadIdx.x;
    if (idx >= N_TOTAL * C_DIM) return;
    int hw = idx & (HW - 1);
    int c = (idx >> 10) & (C_DIM - 1);
    int b = idx >> 17;
    int id = g_ids[b * HW + hw];
    outq[idx] = w[id * C_DIM + c];
}

// ---------------- K6b: EMA update ----------------
__global__ void neww_kernel(const float* __restrict__ w, float* __restrict__ outw) {
    int idx = blockIdx.x * 256 + threadIdx.x;
    if (idx >= K_CODES * C_DIM) return;
    int k = idx >> 7;
    float cnt = g_counts[k];
    float mean = g_sums[idx] / (cnt + 1e-12f);
    outw[idx] = 0.99f * w[idx] + 0.01f * mean;
}

// ---------------------------------------------------------------------------
extern "C" void kernel_launch(void* const* d_in, const int* in_sizes, int n_in,
                              void* d_out, int out_size) {
    const float* enc = (const float*)d_in[0];
    const float* w   = (const float*)d_in[1];
    float* out     = (float*)d_out;
    float* out_ids = out;
    float* out_q   = out + N_TOTAL;
    float* out_w   = out + N_TOTAL + N_TOTAL * C_DIM;

    cudaFuncSetAttribute(dist_kernel,
                         cudaFuncAttributeMaxDynamicSharedMemorySize, DSMEM_BYTES);

    split_w_kernel<<<(K_CODES * C_DIM) / 256, 256>>>(w);
    sumw2_kernel<<<K_CODES / 8, 256>>>(w);
    prep_x_kernel<<<N_TOTAL / 64, 256>>>(enc);
    zero_kernel<<<(K_CODES * C_DIM + 255) / 256, 256>>>();
    dist_kernel<<<dim3(K_CODES / 256, N_TOTAL / 128), 256, DSMEM_BYTES>>>();
    ids_kernel<<<N_TOTAL / 256, 256>>>(out_ids);
    scatter_kernel<<<N_TOTAL / 128, 128>>>(enc);
    q_kernel<<<(N_TOTAL * C_DIM + 255) / 256, 256>>>(w, out_q);
    neww_kernel<<<(K_CODES * C_DIM + 255) / 256, 256>>>(w, out_w);
}